// round 4
// baseline (speedup 1.0000x reference)
#include <cuda_runtime.h>

// snnTorch Leaky SNN scan (v3 — stable candidate awaiting first bench):
//   reset_t = H(mem_{t-1} - 1)
//   mem_t   = 0.5*mem_{t-1} + x_t - reset_t
//   spk_t   = H(mem_t - 1)
// x, spk: [T=128, B, N] float32 (nominal B*N = 262144). Serial in T,
// parallel over B*N. Pure HBM stream: 134 MB in + 134 MB out
// -> floor ~42-50 us on GB300 at the ~6300 B/cyc LTS cap.

#define T_STEPS 128

__global__ __launch_bounds__(128) void snn_leaky_kernel(
    const float4* __restrict__ x, float4* __restrict__ out, int nv)
{
    const int tid = blockIdx.x * blockDim.x + threadIdx.x;
    if (tid >= nv) return;

    const float4* xp = x + tid;
    float4*       op = out + tid;

    float4 mem = make_float4(0.f, 0.f, 0.f, 0.f);

    #pragma unroll 8
    for (int t = 0; t < T_STEPS; t++) {
        // x[t] load is independent of the mem recurrence -> ptxas
        // front-batches the unrolled group's loads (MLP ~ 8).
        // Evict-first: every byte is read exactly once.
        const float4 cur = __ldcs(xp + (size_t)t * nv);

        float4 spk;
        {
            const float reset = (mem.x > 1.0f) ? 1.0f : 0.0f;
            mem.x = 0.5f * mem.x + cur.x - reset;
            spk.x = (mem.x > 1.0f) ? 1.0f : 0.0f;
        }
        {
            const float reset = (mem.y > 1.0f) ? 1.0f : 0.0f;
            mem.y = 0.5f * mem.y + cur.y - reset;
            spk.y = (mem.y > 1.0f) ? 1.0f : 0.0f;
        }
        {
            const float reset = (mem.z > 1.0f) ? 1.0f : 0.0f;
            mem.z = 0.5f * mem.z + cur.z - reset;
            spk.z = (mem.z > 1.0f) ? 1.0f : 0.0f;
        }
        {
            const float reset = (mem.w > 1.0f) ? 1.0f : 0.0f;
            mem.w = 0.5f * mem.w + cur.w - reset;
            spk.w = (mem.w > 1.0f) ? 1.0f : 0.0f;
        }

        // Streaming store: output never re-read by this kernel.
        __stcs(op + (size_t)t * nv, spk);
    }
}

extern "C" void kernel_launch(void* const* d_in, const int* in_sizes, int n_in,
                              void* d_out, int out_size)
{
    (void)n_in; (void)out_size;
    const float4* x = (const float4*)d_in[0];
    float4*       o = (float4*)d_out;

    // total elements = T * B * N; B*N is divisible by 4 (N = 4096 nominal)
    const int bn = in_sizes[0] / T_STEPS;   // neurons per timestep
    const int nv = bn / 4;                  // float4 lanes per timestep

    const int threads = 128;
    const int blocks  = (nv + threads - 1) / threads;
    snn_leaky_kernel<<<blocks, threads>>>(x, o, nv);
}

// round 7
// speedup vs baseline: 1.7834x; 1.7834x over previous
#include <cuda_runtime.h>

// snnTorch Leaky SNN scan (v4 — explicit 8-deep prefetch pipeline):
//   reset_t = H(mem_{t-1} - 1)
//   mem_t   = 0.5*mem_{t-1} + x_t - reset_t
//   spk_t   = H(mem_t - 1)
// x, spk: [T=128, B, N] float32. Serial in T, parallel over B*N.
// R4 profile showed latency-bound (DRAM 36%, regs=24 -> ptxas didn't
// front-batch loads). This version forces MLP=8 via a register ring.

#define T_STEPS 128
#define DEPTH   8          // prefetch distance (power of 2)

__global__ __launch_bounds__(128) void snn_leaky_kernel(
    const float4* __restrict__ x, float4* __restrict__ out, int nv)
{
    const int tid = blockIdx.x * blockDim.x + threadIdx.x;
    if (tid >= nv) return;

    const float4* xp = x + tid;
    float4*       op = out + tid;

    // Prime the pipeline: 8 independent LDG.E.128 in flight, guaranteed.
    float4 buf[DEPTH];
    #pragma unroll
    for (int i = 0; i < DEPTH; i++)
        buf[i] = __ldcs(xp + (size_t)i * nv);

    float4 mem = make_float4(0.f, 0.f, 0.f, 0.f);

    #pragma unroll 8
    for (int t = 0; t < T_STEPS; t++) {
        const float4 cur = buf[t & (DEPTH - 1)];

        // Refill the ring slot immediately -> keeps 8 loads outstanding.
        const int tn = t + DEPTH;
        if (tn < T_STEPS)
            buf[t & (DEPTH - 1)] = __ldcs(xp + (size_t)tn * nv);

        float4 spk;
        {
            const float reset = (mem.x > 1.0f) ? 1.0f : 0.0f;
            mem.x = 0.5f * mem.x + cur.x - reset;
            spk.x = (mem.x > 1.0f) ? 1.0f : 0.0f;
        }
        {
            const float reset = (mem.y > 1.0f) ? 1.0f : 0.0f;
            mem.y = 0.5f * mem.y + cur.y - reset;
            spk.y = (mem.y > 1.0f) ? 1.0f : 0.0f;
        }
        {
            const float reset = (mem.z > 1.0f) ? 1.0f : 0.0f;
            mem.z = 0.5f * mem.z + cur.z - reset;
            spk.z = (mem.z > 1.0f) ? 1.0f : 0.0f;
        }
        {
            const float reset = (mem.w > 1.0f) ? 1.0f : 0.0f;
            mem.w = 0.5f * mem.w + cur.w - reset;
            spk.w = (mem.w > 1.0f) ? 1.0f : 0.0f;
        }

        // Streaming store: output never re-read by this kernel.
        __stcs(op + (size_t)t * nv, spk);
    }
}

extern "C" void kernel_launch(void* const* d_in, const int* in_sizes, int n_in,
                              void* d_out, int out_size)
{
    (void)n_in; (void)out_size;
    const float4* x = (const float4*)d_in[0];
    float4*       o = (float4*)d_out;

    // total elements = T * B * N; B*N divisible by 4 (N = 4096 nominal)
    const int bn = in_sizes[0] / T_STEPS;   // neurons per timestep
    const int nv = bn / 4;                  // float4 lanes per timestep

    const int threads = 128;
    const int blocks  = (nv + threads - 1) / threads;
    snn_leaky_kernel<<<blocks, threads>>>(x, o, nv);
}

// round 9
// speedup vs baseline: 1.8461x; 1.0351x over previous
#include <cuda_runtime.h>

// snnTorch Leaky SNN scan (v5 — v4 ring + fine-grained grid for SM balance):
//   reset_t = H(mem_{t-1} - 1)
//   mem_t   = 0.5*mem_{t-1} + x_t - reset_t
//   spk_t   = H(mem_t - 1)
// v4 (512x128, MLP-8 ring) hit 47.1us, DRAM 72%. Remaining loss: CTA
// imbalance (68 SMs x 4 CTAs vs 80 x 3 => 33% skew). 64-thread CTAs give
// 1024 CTAs -> 136 SMs x 7 vs 12 x 6 => ~1% skew at the max.

#define T_STEPS 128
#define DEPTH   8          // prefetch distance (power of 2)

__global__ __launch_bounds__(64) void snn_leaky_kernel(
    const float4* __restrict__ x, float4* __restrict__ out, int nv)
{
    const int tid = blockIdx.x * blockDim.x + threadIdx.x;
    if (tid >= nv) return;

    const float4* xp = x + tid;
    float4*       op = out + tid;

    // Prime the pipeline: 8 independent LDG.E.128 in flight, guaranteed.
    float4 buf[DEPTH];
    #pragma unroll
    for (int i = 0; i < DEPTH; i++)
        buf[i] = __ldcs(xp + (size_t)i * nv);

    float4 mem = make_float4(0.f, 0.f, 0.f, 0.f);

    #pragma unroll 8
    for (int t = 0; t < T_STEPS; t++) {
        const float4 cur = buf[t & (DEPTH - 1)];

        // Refill the ring slot immediately -> keeps 8 loads outstanding.
        const int tn = t + DEPTH;
        if (tn < T_STEPS)
            buf[t & (DEPTH - 1)] = __ldcs(xp + (size_t)tn * nv);

        float4 spk;
        {
            const float reset = (mem.x > 1.0f) ? 1.0f : 0.0f;
            mem.x = 0.5f * mem.x + cur.x - reset;
            spk.x = (mem.x > 1.0f) ? 1.0f : 0.0f;
        }
        {
            const float reset = (mem.y > 1.0f) ? 1.0f : 0.0f;
            mem.y = 0.5f * mem.y + cur.y - reset;
            spk.y = (mem.y > 1.0f) ? 1.0f : 0.0f;
        }
        {
            const float reset = (mem.z > 1.0f) ? 1.0f : 0.0f;
            mem.z = 0.5f * mem.z + cur.z - reset;
            spk.z = (mem.z > 1.0f) ? 1.0f : 0.0f;
        }
        {
            const float reset = (mem.w > 1.0f) ? 1.0f : 0.0f;
            mem.w = 0.5f * mem.w + cur.w - reset;
            spk.w = (mem.w > 1.0f) ? 1.0f : 0.0f;
        }

        // Streaming store: output never re-read by this kernel.
        __stcs(op + (size_t)t * nv, spk);
    }
}

extern "C" void kernel_launch(void* const* d_in, const int* in_sizes, int n_in,
                              void* d_out, int out_size)
{
    (void)n_in; (void)out_size;
    const float4* x = (const float4*)d_in[0];
    float4*       o = (float4*)d_out;

    // total elements = T * B * N; B*N divisible by 4 (N = 4096 nominal)
    const int bn = in_sizes[0] / T_STEPS;   // neurons per timestep
    const int nv = bn / 4;                  // float4 lanes per timestep

    const int threads = 64;                 // fine-grained CTAs for balance
    const int blocks  = (nv + threads - 1) / threads;
    snn_leaky_kernel<<<blocks, threads>>>(x, o, nv);
}